// round 5
// baseline (speedup 1.0000x reference)
#include <cuda_runtime.h>
#include <cuda_bf16.h>
#include <cstdint>

// Embedding gather: out[t, :] = W_E[tokens[t], :]
// tokens: int32 [32768], W_E: float32 [50257, 768], out: float32 [32768, 768]
//
// R4 -> R5: one-shot bulk CTAs averaged too little in-flight traffic (DRAM 58%).
// Now PERSISTENT single-warp CTAs (grid 888 = 148*6, 36KB smem, 6 CTAs/SM) run a
// 3-stage bulk-copy pipeline over groups of 4 rows: each iteration issues the
// next group's loads before waiting on (and storing) the previous group, so the
// copy engine is continuously fed and load latency is fully overlapped.

#define ROW_BYTES 3072
#define RPG       4                       // rows per group (stage)
#define STAGES    3
#define STAGE_BYTES (RPG * ROW_BYTES)     // 12288
#define SMEM_BYTES  (STAGES * STAGE_BYTES) // 36864
#define NCTAS     (148 * 6)

__device__ __forceinline__ uint32_t smem_u32(const void* p) {
    uint32_t a;
    asm("{ .reg .u64 t; cvta.to.shared.u64 t, %1; cvt.u32.u64 %0, t; }"
        : "=r"(a) : "l"(p));
    return a;
}

__device__ __forceinline__ void mbar_wait(uint32_t mbar_a, uint32_t phase) {
    asm volatile(
        "{\n\t"
        ".reg .pred P1;\n\t"
        "WAIT_LOOP_%=:\n\t"
        "mbarrier.try_wait.parity.shared.b64 P1, [%0], %1, 0x989680;\n\t"
        "@P1 bra.uni WAIT_DONE_%=;\n\t"
        "bra.uni WAIT_LOOP_%=;\n\t"
        "WAIT_DONE_%=:\n\t"
        "}"
        :: "r"(mbar_a), "r"(phase) : "memory");
}

__global__ __launch_bounds__(32) void embed_pers_kernel(
    const int* __restrict__ tokens,
    const unsigned char* __restrict__ W,     // byte view of W_E
    unsigned char* __restrict__ out,         // byte view of out
    int n_tok)
{
    extern __shared__ __align__(128) unsigned char sbuf[];
    __shared__ __align__(16) uint64_t mbar[STAGES];

    if (threadIdx.x != 0) return;            // single issuing thread per CTA

    const int ngroups = (n_tok + RPG - 1) / RPG;
    int g = blockIdx.x;
    if (g >= ngroups) return;

    // init mbarriers (this CTA's only thread uses them)
    #pragma unroll
    for (int s = 0; s < STAGES; ++s)
        asm volatile("mbarrier.init.shared.b64 [%0], 1;"
                     :: "r"(smem_u32(&mbar[s])) : "memory");
    asm volatile("fence.proxy.async.shared::cta;" ::: "memory");

    const uint32_t sbase = smem_u32(sbuf);
    uint32_t mbar_a[STAGES];
    #pragma unroll
    for (int s = 0; s < STAGES; ++s) mbar_a[s] = smem_u32(&mbar[s]);

    uint32_t phases = 0;                     // one phase bit per stage

    // preload indices for first group
    int rows_cur[RPG], rows_nxt[RPG];
    {
        const int t0 = g * RPG;
        const int cnt = (n_tok - t0 < RPG) ? (n_tok - t0) : RPG;
        #pragma unroll
        for (int r = 0; r < RPG; ++r)
            rows_cur[r] = (r < cnt) ? __ldg(tokens + t0 + r) : 0;
    }

    int prev_t0 = 0, prev_cnt = 0;
    int it = 0;

    for (; g < ngroups; g += gridDim.x, ++it) {
        const int t0  = g * RPG;
        const int cnt = (n_tok - t0 < RPG) ? (n_tok - t0) : RPG;
        const int buf = it % STAGES;
        const uint32_t sstage = sbase + buf * STAGE_BYTES;

        // Ensure this buffer's previous stores have finished reading smem.
        // (ring depth 3 => the store group using this buf is >= 2 commits old)
        asm volatile("cp.async.bulk.wait_group.read 1;" ::: "memory");

        // Arm and issue this group's loads.
        asm volatile("mbarrier.arrive.expect_tx.shared.b64 _, [%0], %1;"
                     :: "r"(mbar_a[buf]), "r"((uint32_t)(cnt * ROW_BYTES)) : "memory");
        #pragma unroll
        for (int r = 0; r < RPG; ++r) {
            if (r < cnt) {
                const unsigned char* src = W + (size_t)rows_cur[r] * ROW_BYTES;
                asm volatile(
                    "cp.async.bulk.shared::cta.global.mbarrier::complete_tx::bytes "
                    "[%0], [%1], %2, [%3];"
                    :: "r"(sstage + r * ROW_BYTES), "l"(src),
                       "r"((uint32_t)ROW_BYTES), "r"(mbar_a[buf])
                    : "memory");
            }
        }

        // Prefetch next group's token indices (used next iteration).
        const int gn = g + gridDim.x;
        if (gn < ngroups) {
            const int tn0 = gn * RPG;
            const int cntn = (n_tok - tn0 < RPG) ? (n_tok - tn0) : RPG;
            #pragma unroll
            for (int r = 0; r < RPG; ++r)
                rows_nxt[r] = (r < cntn) ? __ldg(tokens + tn0 + r) : 0;
        }

        // Wait for the PREVIOUS group's loads, then store it.
        if (it > 0) {
            const int pbuf = (it - 1) % STAGES;
            const uint32_t ph = (phases >> pbuf) & 1u;
            mbar_wait(mbar_a[pbuf], ph);
            phases ^= (1u << pbuf);

            const uint32_t pstage = sbase + pbuf * STAGE_BYTES;
            #pragma unroll
            for (int r = 0; r < RPG; ++r) {
                if (r < prev_cnt) {
                    unsigned char* dst = out + (size_t)(prev_t0 + r) * ROW_BYTES;
                    asm volatile(
                        "cp.async.bulk.global.shared::cta.bulk_group [%0], [%1], %2;"
                        :: "l"(dst), "r"(pstage + r * ROW_BYTES),
                           "r"((uint32_t)ROW_BYTES)
                        : "memory");
                }
            }
            asm volatile("cp.async.bulk.commit_group;" ::: "memory");
        }

        prev_t0 = t0; prev_cnt = cnt;
        #pragma unroll
        for (int r = 0; r < RPG; ++r) rows_cur[r] = rows_nxt[r];
    }

    // Tail: drain last group.
    {
        const int pbuf = (it - 1) % STAGES;
        const uint32_t ph = (phases >> pbuf) & 1u;
        mbar_wait(mbar_a[pbuf], ph);

        const uint32_t pstage = sbase + pbuf * STAGE_BYTES;
        #pragma unroll
        for (int r = 0; r < RPG; ++r) {
            if (r < prev_cnt) {
                unsigned char* dst = out + (size_t)(prev_t0 + r) * ROW_BYTES;
                asm volatile(
                    "cp.async.bulk.global.shared::cta.bulk_group [%0], [%1], %2;"
                    :: "l"(dst), "r"(pstage + r * ROW_BYTES),
                       "r"((uint32_t)ROW_BYTES)
                    : "memory");
            }
        }
        asm volatile("cp.async.bulk.commit_group;" ::: "memory");
        asm volatile("cp.async.bulk.wait_group 0;" ::: "memory");
    }
}

extern "C" void kernel_launch(void* const* d_in, const int* in_sizes, int n_in,
                              void* d_out, int out_size)
{
    const int* tokens      = (const int*)d_in[0];
    const unsigned char* W = (const unsigned char*)d_in[1];
    unsigned char* out     = (unsigned char*)d_out;

    const int n_tok = in_sizes[0];   // 32768

    embed_pers_kernel<<<NCTAS, 32, SMEM_BYTES>>>(tokens, W, out, n_tok);
}

// round 6
// speedup vs baseline: 1.0028x; 1.0028x over previous
#include <cuda_runtime.h>
#include <cuda_bf16.h>
#include <cstdint>

// Embedding gather: out[t, :] = W_E[tokens[t], :]
// tokens: int32 [32768], W_E: float32 [50257, 768], out: float32 [32768, 768]
//
// R5 -> R6: bulk-engine paths were issue/handoff-limited (DRAM 53-58%); the
// register LDG path was reg-file-limited (MLP_eff < 8, DRAM 62%). This version
// holds in-flight bytes in SMEM via cp.async (LDGSTS): persistent CTAs
// (grid 296, 192 thr), 4-stage ring of 8-row 24KB buffers (96KB smem,
// 2 CTAs/SM -> ~190KB/SM of loads in flight). Each thread owns byte-offset
// t*16 of every row, so drain needs no __syncthreads: per-thread
// cp.async.wait_group guarantees visibility of its own copies.

#define ROW_BYTES 3072
#define T         192                     // threads = ROW_BYTES/16
#define RPG       8                       // rows per group
#define STAGES    4
#define STAGE_BYTES (RPG * ROW_BYTES)     // 24576
#define SMEM_BYTES  (STAGES * STAGE_BYTES) // 98304
#define NCTAS     (148 * 2)

__device__ __forceinline__ uint32_t smem_u32(const void* p) {
    uint32_t a;
    asm("{ .reg .u64 t; cvta.to.shared.u64 t, %1; cvt.u32.u64 %0, t; }"
        : "=r"(a) : "l"(p));
    return a;
}

__device__ __forceinline__ void cp_async16(uint32_t dst_smem, const void* src) {
    asm volatile("cp.async.cg.shared.global [%0], [%1], 16;"
                 :: "r"(dst_smem), "l"(src) : "memory");
}

__device__ __forceinline__ void cp_commit() {
    asm volatile("cp.async.commit_group;" ::: "memory");
}

// Wait until at most N groups remain outstanding (runtime N via switch on
// small constant range; STAGES=4 so N in [0,3]).
__device__ __forceinline__ void cp_wait(int n) {
    switch (n) {
        case 0: asm volatile("cp.async.wait_group 0;" ::: "memory"); break;
        case 1: asm volatile("cp.async.wait_group 1;" ::: "memory"); break;
        case 2: asm volatile("cp.async.wait_group 2;" ::: "memory"); break;
        default: asm volatile("cp.async.wait_group 3;" ::: "memory"); break;
    }
}

__global__ __launch_bounds__(T) void embed_cpasync_kernel(
    const int* __restrict__ tokens,
    const unsigned char* __restrict__ W,     // byte view of W_E
    unsigned char* __restrict__ out,         // byte view of out
    int n_tok)
{
    extern __shared__ __align__(128) unsigned char sbuf[];

    const int t      = threadIdx.x;
    const int coff   = t * 16;               // this thread's byte offset in a row
    const uint32_t sbase = smem_u32(sbuf);

    const int ngroups = (n_tok + RPG - 1) / RPG;
    // my groups: g = blockIdx.x + j * gridDim.x, j = 0..my_ng-1
    int my_ng = 0;
    {
        if (blockIdx.x < ngroups)
            my_ng = (ngroups - blockIdx.x + gridDim.x - 1) / gridDim.x;
    }
    if (my_ng == 0) return;

    int issued = 0, drained = 0;

    while (drained < my_ng) {
        // Fill pipeline: keep up to STAGES groups outstanding.
        while (issued < my_ng && issued - drained < STAGES) {
            const int g   = blockIdx.x + issued * gridDim.x;
            const int t0  = g * RPG;
            const int cnt = (n_tok - t0 < RPG) ? (n_tok - t0) : RPG;
            const uint32_t sstage = sbase + (issued % STAGES) * STAGE_BYTES;

            #pragma unroll
            for (int r = 0; r < RPG; ++r) {
                if (r < cnt) {
                    const int row = __ldg(tokens + t0 + r);   // uniform: L1 broadcast
                    cp_async16(sstage + r * ROW_BYTES + coff,
                               W + (size_t)row * ROW_BYTES + coff);
                }
            }
            cp_commit();
            ++issued;
        }

        // Drain oldest group.
        cp_wait(issued - drained - 1);
        {
            const int g   = blockIdx.x + drained * gridDim.x;
            const int t0  = g * RPG;
            const int cnt = (n_tok - t0 < RPG) ? (n_tok - t0) : RPG;
            const unsigned char* sstage =
                sbuf + (drained % STAGES) * STAGE_BYTES;

            #pragma unroll
            for (int r = 0; r < RPG; ++r) {
                if (r < cnt) {
                    float4 v = *reinterpret_cast<const float4*>(
                        sstage + r * ROW_BYTES + coff);
                    *reinterpret_cast<float4*>(
                        out + (size_t)(t0 + r) * ROW_BYTES + coff) = v;
                }
            }
        }
        ++drained;
    }
}

extern "C" void kernel_launch(void* const* d_in, const int* in_sizes, int n_in,
                              void* d_out, int out_size)
{
    const int* tokens      = (const int*)d_in[0];
    const unsigned char* W = (const unsigned char*)d_in[1];
    unsigned char* out     = (unsigned char*)d_out;

    const int n_tok = in_sizes[0];   // 32768

    // 96KB dynamic smem needs an opt-in above the 48KB default.
    static bool attr_set = false;
    if (!attr_set) {
        cudaFuncSetAttribute(embed_cpasync_kernel,
                             cudaFuncAttributeMaxDynamicSharedMemorySize,
                             SMEM_BYTES);
        attr_set = true;
    }

    embed_cpasync_kernel<<<NCTAS, T, SMEM_BYTES>>>(tokens, W, out, n_tok);
}

// round 8
// speedup vs baseline: 1.1178x; 1.1148x over previous
#include <cuda_runtime.h>
#include <cuda_bf16.h>
#include <cstdint>

// Embedding gather: out[t, :] = W_E[tokens[t], :]
// tokens: int32 [32768], W_E: float32 [50257, 768], out: float32 [32768, 768]
//
// R7 -> R8: ptxas rejects immediate-form .L2::evict_last on v4.f32 (sm_103a
// allows it only on v8.b32/v4.b64). Use the createpolicy + L2::cache_hint form
// instead (dtype-agnostic):
//   reads:  createpolicy.fractional.L2::evict_last -> ld.global.nc...cache_hint
//   writes: st.global.cs (streaming, evict-first)
// Goal: pin W_E's working set in L2 across graph replays, make the DRAM stream
// write-dominated. 8 tokens/CTA with batched 8-deep float4 load MLP.

#define D_MODEL 768
#define V4 (D_MODEL / 4)   // 192 float4 per row
#define U 8                // tokens per CTA

__global__ void embed_gather_kernel(
    const int* __restrict__ tokens,
    const float4* __restrict__ W,
    float4* __restrict__ out,
    int n_tok)
{
    const int col = threadIdx.x;
    const int t0  = blockIdx.x * U;

    // L2 policy: keep W_E lines resident (evict_last on hit+miss).
    uint64_t pol;
    asm("createpolicy.fractional.L2::evict_last.b64 %0, 1.0;" : "=l"(pol));

    if (t0 + U <= n_tok) {
        int rows[U];
#pragma unroll
        for (int u = 0; u < U; ++u)
            rows[u] = __ldg(tokens + t0 + u);       // uniform per block

        float4 v[U];
#pragma unroll
        for (int u = 0; u < U; ++u) {
            const float4* src = W + (size_t)rows[u] * V4 + col;
            asm volatile(
                "ld.global.nc.L2::cache_hint.v4.f32 {%0, %1, %2, %3}, [%4], %5;"
                : "=f"(v[u].x), "=f"(v[u].y), "=f"(v[u].z), "=f"(v[u].w)
                : "l"(src), "l"(pol));
        }

#pragma unroll
        for (int u = 0; u < U; ++u) {
            float4* dst = out + (size_t)(t0 + u) * V4 + col;
            asm volatile(
                "st.global.cs.v4.f32 [%0], {%1, %2, %3, %4};"
                :: "l"(dst), "f"(v[u].x), "f"(v[u].y), "f"(v[u].z), "f"(v[u].w)
                : "memory");
        }
    } else {
        for (int t = t0; t < n_tok; ++t) {
            int row = __ldg(tokens + t);
            float4 v;
            const float4* src = W + (size_t)row * V4 + col;
            asm volatile(
                "ld.global.nc.L2::cache_hint.v4.f32 {%0, %1, %2, %3}, [%4], %5;"
                : "=f"(v.x), "=f"(v.y), "=f"(v.z), "=f"(v.w)
                : "l"(src), "l"(pol));
            float4* dst = out + (size_t)t * V4 + col;
            asm volatile(
                "st.global.cs.v4.f32 [%0], {%1, %2, %3, %4};"
                :: "l"(dst), "f"(v.x), "f"(v.y), "f"(v.z), "f"(v.w)
                : "memory");
        }
    }
}

extern "C" void kernel_launch(void* const* d_in, const int* in_sizes, int n_in,
                              void* d_out, int out_size)
{
    const int* tokens = (const int*)d_in[0];
    const float4* W   = (const float4*)d_in[1];
    float4* out       = (float4*)d_out;

    const int n_tok = in_sizes[0];   // 32768
    const int grid  = (n_tok + U - 1) / U;

    embed_gather_kernel<<<grid, V4>>>(tokens, W, out, n_tok);
}